// round 1
// baseline (speedup 1.0000x reference)
#include <cuda_runtime.h>
#include <math_constants.h>

// Problem constants (fixed shapes: b=2,h=16,s=4096,d=64,m=256)
constexpr int D       = 64;
constexpr int M       = 256;
constexpr int TOKENS  = 2 * 16 * 4096;   // 131072 tokens per tensor
constexpr int TPB     = 128;             // tokens per block (divides 4096 -> no bh crossing)
constexpr int TB      = 4;               // tokens per inner iteration
constexpr float NORMALIZER = 0.35355339059327379f; // 64^-0.25 = 2^-1.5
constexpr float HALF_N2    = 0.0625f;    // 0.5 * normalizer^2
constexpr float RATIO      = 0.0625f;    // 256^-0.5
constexpr float EPSV       = 1e-4f;

// Per-(b,h) running max of k data_dash (32 slabs)
__device__ float g_stab[32];

__global__ void init_stab() {
    if (threadIdx.x < 32) g_stab[threadIdx.x] = -CUDART_INF_F;
}

__device__ __forceinline__ void atomicMaxFloat(float* addr, float val) {
    int* ai = (int*)addr;
    int old = *ai;
    while (__int_as_float(old) < val) {
        int assumed = old;
        old = atomicCAS(ai, assumed, __float_as_int(val));
        if (old == assumed) break;
    }
}

// thread tid owns projection row tid (m == blockDim == 256).
// Block processes TPB consecutive tokens, TB at a time.
template<bool IS_QUERY>
__global__ __launch_bounds__(256, 2) void proj_kernel(
    const float* __restrict__ data,
    const float* __restrict__ proj,
    float* __restrict__ out)
{
    __shared__ float4 sx[TB][D / 4];
    __shared__ float  sdiag[TB];
    __shared__ float  sred[8][TB];
    __shared__ float  sstab[TB];

    const int tid  = threadIdx.x;
    const int lane = tid & 31;
    const int warp = tid >> 5;

    // Load this thread's projection row, fold in data_normalizer.
    float p[D];
    {
        const float4* pr = reinterpret_cast<const float4*>(proj) + tid * (D / 4);
        #pragma unroll
        for (int i = 0; i < D / 4; ++i) {
            float4 v = pr[i];
            p[4*i+0] = v.x * NORMALIZER;
            p[4*i+1] = v.y * NORMALIZER;
            p[4*i+2] = v.z * NORMALIZER;
            p[4*i+3] = v.w * NORMALIZER;
        }
    }

    const long long tok0 = (long long)blockIdx.x * TPB;
    float kmax = -CUDART_INF_F;

    for (int it = 0; it < TPB; it += TB) {
        const long long tbase = tok0 + it;

        // Stage TB tokens into smem + compute diag via 16-lane shuffle reduce.
        if (tid < TB * 16) {
            int tt = tid >> 4, ii = tid & 15;
            float4 v = reinterpret_cast<const float4*>(data + (tbase + tt) * D)[ii];
            sx[tt][ii] = v;
            float sq = v.x*v.x + v.y*v.y + v.z*v.z + v.w*v.w;
            sq += __shfl_down_sync(0xffffffffu, sq, 8, 16);
            sq += __shfl_down_sync(0xffffffffu, sq, 4, 16);
            sq += __shfl_down_sync(0xffffffffu, sq, 2, 16);
            sq += __shfl_down_sync(0xffffffffu, sq, 1, 16);
            if (ii == 0) sdiag[tt] = HALF_N2 * sq;
        }
        __syncthreads();

        // 4 dot products of length 64, p in regs, x broadcast from smem.
        float acc[TB];
        #pragma unroll
        for (int t = 0; t < TB; ++t) acc[t] = 0.0f;
        #pragma unroll
        for (int i = 0; i < D / 4; ++i) {
            const float px = p[4*i+0], py = p[4*i+1], pz = p[4*i+2], pw = p[4*i+3];
            #pragma unroll
            for (int t = 0; t < TB; ++t) {
                float4 xv = sx[t][i];
                acc[t] = fmaf(px, xv.x, acc[t]);
                acc[t] = fmaf(py, xv.y, acc[t]);
                acc[t] = fmaf(pz, xv.z, acc[t]);
                acc[t] = fmaf(pw, xv.w, acc[t]);
            }
        }

        if (IS_QUERY) {
            // per-token max over all 256 features (block-wide reduction)
            float mx[TB];
            #pragma unroll
            for (int t = 0; t < TB; ++t) mx[t] = acc[t];
            #pragma unroll
            for (int off = 16; off; off >>= 1) {
                #pragma unroll
                for (int t = 0; t < TB; ++t)
                    mx[t] = fmaxf(mx[t], __shfl_xor_sync(0xffffffffu, mx[t], off));
            }
            if (lane == 0) {
                #pragma unroll
                for (int t = 0; t < TB; ++t) sred[warp][t] = mx[t];
            }
            __syncthreads();
            if (tid < TB) {
                float m2 = sred[0][tid];
                #pragma unroll
                for (int w = 1; w < 8; ++w) m2 = fmaxf(m2, sred[w][tid]);
                sstab[tid] = m2;
            }
            __syncthreads();
            #pragma unroll
            for (int t = 0; t < TB; ++t) {
                float e = __expf(acc[t] - sdiag[t] - sstab[t]);
                out[(tbase + t) * M + tid] = RATIO * (e + EPSV);
            }
            __syncthreads();  // protect sx/sdiag for next iteration
        } else {
            #pragma unroll
            for (int t = 0; t < TB; ++t) {
                kmax = fmaxf(kmax, acc[t]);
                out[(tbase + t) * M + tid] = acc[t] - sdiag[t];  // scratch: dash - diag
            }
            __syncthreads();  // protect sx/sdiag for next iteration
        }
    }

    if (!IS_QUERY) {
        #pragma unroll
        for (int off = 16; off; off >>= 1)
            kmax = fmaxf(kmax, __shfl_xor_sync(0xffffffffu, kmax, off));
        if (lane == 0) sred[warp][0] = kmax;
        __syncthreads();
        if (tid == 0) {
            float m2 = sred[0][0];
            #pragma unroll
            for (int w = 1; w < 8; ++w) m2 = fmaxf(m2, sred[w][0]);
            atomicMaxFloat(&g_stab[blockIdx.x >> 5], m2);  // 32 blocks per (b,h)
        }
    }
}

// Elementwise pass 2 for k: out = ratio * (exp(v - stab[bh]) + eps)
__global__ void finalize_k(float* __restrict__ kout) {
    long long i4 = (long long)blockIdx.x * blockDim.x + threadIdx.x;  // float4 index
    float4* p4 = reinterpret_cast<float4*>(kout);
    float4 v = p4[i4];
    int bh = (int)((i4 * 4) >> 20);  // 4096*256 = 2^20 elements per (b,h)
    float stab = g_stab[bh];
    v.x = RATIO * (__expf(v.x - stab) + EPSV);
    v.y = RATIO * (__expf(v.y - stab) + EPSV);
    v.z = RATIO * (__expf(v.z - stab) + EPSV);
    v.w = RATIO * (__expf(v.w - stab) + EPSV);
    p4[i4] = v;
}

extern "C" void kernel_launch(void* const* d_in, const int* in_sizes, int n_in,
                              void* d_out, int out_size) {
    const float* q    = (const float*)d_in[0];
    const float* k    = (const float*)d_in[1];
    const float* proj = (const float*)d_in[2];

    float* out_q = (float*)d_out;
    float* out_k = out_q + (long long)TOKENS * M;  // q_prime first, then k_prime

    init_stab<<<1, 32>>>();
    proj_kernel<true ><<<TOKENS / TPB, 256>>>(q, proj, out_q);
    proj_kernel<false><<<TOKENS / TPB, 256>>>(k, proj, out_k);

    const long long kelems = (long long)TOKENS * M;        // 33,554,432
    finalize_k<<<(int)(kelems / 4 / 256), 256>>>(out_k);   // 32768 blocks
}

// round 2
// speedup vs baseline: 1.1518x; 1.1518x over previous
#include <cuda_runtime.h>
#include <math_constants.h>

// Problem constants (fixed shapes: b=2,h=16,s=4096,d=64,m=256)
constexpr int D       = 64;
constexpr int M       = 256;
constexpr int TOKENS  = 2 * 16 * 4096;   // 131072 tokens per tensor
constexpr int TPB     = 64;              // tokens per block (divides 4096 -> no bh crossing)
constexpr int TB      = 8;               // tokens per inner iteration
constexpr float NORMALIZER = 0.35355339059327379f; // 64^-0.25 = 2^-1.5
constexpr float HALF_N2    = 0.0625f;    // 0.5 * normalizer^2
constexpr float RATIO      = 0.0625f;    // 256^-0.5
constexpr float EPSV       = 1e-4f;
constexpr float OFFSET     = RATIO * EPSV;

// Per-(b,h) running max of k data_dash (32 slabs) and derived scale
__device__ float g_stab[32];
__device__ float g_scale[32];

__global__ void init_stab() {
    if (threadIdx.x < 32) g_stab[threadIdx.x] = -CUDART_INF_F;
}

__global__ void prep_scale() {
    if (threadIdx.x < 32) g_scale[threadIdx.x] = RATIO * __expf(-g_stab[threadIdx.x]);
}

__device__ __forceinline__ void atomicMaxFloat(float* addr, float val) {
    int* ai = (int*)addr;
    int old = *ai;
    while (__int_as_float(old) < val) {
        int assumed = old;
        old = atomicCAS(ai, assumed, __float_as_int(val));
        if (old == assumed) break;
    }
}

// Packed f32x2 helpers (SASS FFMA2 — only reachable via PTX fma.rn.f32x2)
__device__ __forceinline__ unsigned long long pack2(float lo, float hi) {
    unsigned long long r;
    asm("mov.b64 %0, {%1, %2};" : "=l"(r) : "f"(lo), "f"(hi));
    return r;
}
__device__ __forceinline__ unsigned long long ffma2(unsigned long long a,
                                                    unsigned long long b,
                                                    unsigned long long c) {
    unsigned long long d;
    asm("fma.rn.f32x2 %0, %1, %2, %3;" : "=l"(d) : "l"(a), "l"(b), "l"(c));
    return d;
}
__device__ __forceinline__ float hsum2(unsigned long long v) {
    float lo, hi;
    asm("mov.b64 {%0, %1}, %2;" : "=f"(lo), "=f"(hi) : "l"(v));
    return lo + hi;
}

// thread tid owns projection row tid (m == blockDim == 256), held as 32 packed
// dim-pairs. Block processes TPB consecutive tokens, TB at a time.
template<bool IS_QUERY>
__global__ __launch_bounds__(256, 2) void proj_kernel(
    const float* __restrict__ data,
    const float* __restrict__ proj,
    float* __restrict__ out)
{
    __shared__ float4 sx[TB][D / 4];
    __shared__ float  sdiag[TB];
    __shared__ float  sred[8][TB];
    __shared__ float  sstab[TB];

    const int tid  = threadIdx.x;
    const int lane = tid & 31;
    const int warp = tid >> 5;

    // Load this thread's projection row, fold normalizer, pack dim-pairs.
    unsigned long long p2[D / 2];
    {
        const float4* pr = reinterpret_cast<const float4*>(proj) + tid * (D / 4);
        #pragma unroll
        for (int i = 0; i < D / 4; ++i) {
            float4 v = pr[i];
            p2[2*i+0] = pack2(v.x * NORMALIZER, v.y * NORMALIZER);
            p2[2*i+1] = pack2(v.z * NORMALIZER, v.w * NORMALIZER);
        }
    }

    const long long tok0 = (long long)blockIdx.x * TPB;
    float kmax = -CUDART_INF_F;

    for (int it = 0; it < TPB; it += TB) {
        const long long tbase = tok0 + it;

        // Stage TB tokens into smem + compute diag via 16-lane shuffle reduce.
        if (tid < TB * 16) {
            int tt = tid >> 4, ii = tid & 15;
            float4 v = reinterpret_cast<const float4*>(data + (tbase + tt) * D)[ii];
            sx[tt][ii] = v;
            float sq = v.x*v.x + v.y*v.y + v.z*v.z + v.w*v.w;
            sq += __shfl_down_sync(0xffffffffu, sq, 8, 16);
            sq += __shfl_down_sync(0xffffffffu, sq, 4, 16);
            sq += __shfl_down_sync(0xffffffffu, sq, 2, 16);
            sq += __shfl_down_sync(0xffffffffu, sq, 1, 16);
            if (ii == 0) sdiag[tt] = HALF_N2 * sq;
        }
        __syncthreads();

        // TB dot products of length 64 via packed FFMA2:
        // acc2[t] accumulates (even-dim partial, odd-dim partial).
        unsigned long long acc2[TB];
        #pragma unroll
        for (int t = 0; t < TB; ++t) acc2[t] = 0ull;

        #pragma unroll
        for (int i = 0; i < D / 4; ++i) {
            #pragma unroll
            for (int t = 0; t < TB; ++t) {
                ulonglong2 xq = *reinterpret_cast<const ulonglong2*>(&sx[t][i]);
                acc2[t] = ffma2(p2[2*i+0], xq.x, acc2[t]);
                acc2[t] = ffma2(p2[2*i+1], xq.y, acc2[t]);
            }
        }

        float acc[TB];
        #pragma unroll
        for (int t = 0; t < TB; ++t) acc[t] = hsum2(acc2[t]);

        if (IS_QUERY) {
            // per-token max over all 256 features (block-wide reduction)
            float mx[TB];
            #pragma unroll
            for (int t = 0; t < TB; ++t) mx[t] = acc[t];
            #pragma unroll
            for (int off = 16; off; off >>= 1) {
                #pragma unroll
                for (int t = 0; t < TB; ++t)
                    mx[t] = fmaxf(mx[t], __shfl_xor_sync(0xffffffffu, mx[t], off));
            }
            if (lane == 0) {
                #pragma unroll
                for (int t = 0; t < TB; ++t) sred[warp][t] = mx[t];
            }
            __syncthreads();
            if (tid < TB) {
                float m2 = sred[0][tid];
                #pragma unroll
                for (int w = 1; w < 8; ++w) m2 = fmaxf(m2, sred[w][tid]);
                sstab[tid] = m2;
            }
            __syncthreads();
            #pragma unroll
            for (int t = 0; t < TB; ++t) {
                float e = __expf(acc[t] - sdiag[t] - sstab[t]);
                out[(tbase + t) * M + tid] = RATIO * (e + EPSV);
            }
        } else {
            // store E = exp(dash - diag); global stab applied in finalize_k
            #pragma unroll
            for (int t = 0; t < TB; ++t) {
                kmax = fmaxf(kmax, acc[t]);
                out[(tbase + t) * M + tid] = __expf(acc[t] - sdiag[t]);
            }
        }
        __syncthreads();  // protect sx/sdiag for next iteration
    }

    if (!IS_QUERY) {
        #pragma unroll
        for (int off = 16; off; off >>= 1)
            kmax = fmaxf(kmax, __shfl_xor_sync(0xffffffffu, kmax, off));
        if (lane == 0) sred[warp][0] = kmax;
        __syncthreads();
        if (tid == 0) {
            float m2 = sred[0][0];
            #pragma unroll
            for (int w = 1; w < 8; ++w) m2 = fmaxf(m2, sred[w][0]);
            atomicMaxFloat(&g_stab[blockIdx.x >> 6], m2);  // 64 blocks per (b,h)
        }
    }
}

// Pass 2 for k: out = scale[bh] * E + ratio*eps   (pure FMA, DRAM-bound)
// Two independent float4 per thread for MLP.
__global__ void finalize_k(float* __restrict__ kout) {
    constexpr long long HALF4 = (long long)TOKENS * M / 4 / 2;  // float4 per half
    long long i = (long long)blockIdx.x * blockDim.x + threadIdx.x;
    float4* p4 = reinterpret_cast<float4*>(kout);

    #pragma unroll
    for (int h = 0; h < 2; ++h) {
        long long idx = i + h * HALF4;
        float4 v = p4[idx];
        float scale = g_scale[(int)(idx >> 18)];  // 2^18 float4 per (b,h)
        v.x = fmaf(scale, v.x, OFFSET);
        v.y = fmaf(scale, v.y, OFFSET);
        v.z = fmaf(scale, v.z, OFFSET);
        v.w = fmaf(scale, v.w, OFFSET);
        p4[idx] = v;
    }
}

extern "C" void kernel_launch(void* const* d_in, const int* in_sizes, int n_in,
                              void* d_out, int out_size) {
    const float* q    = (const float*)d_in[0];
    const float* k    = (const float*)d_in[1];
    const float* proj = (const float*)d_in[2];

    float* out_q = (float*)d_out;
    float* out_k = out_q + (long long)TOKENS * M;  // q_prime first, then k_prime

    init_stab<<<1, 32>>>();
    proj_kernel<true ><<<TOKENS / TPB, 256>>>(q, proj, out_q);
    proj_kernel<false><<<TOKENS / TPB, 256>>>(k, proj, out_k);
    prep_scale<<<1, 32>>>();

    constexpr long long HALF4 = (long long)TOKENS * M / 4 / 2;
    finalize_k<<<(int)(HALF4 / 256), 256>>>(out_k);  // 16384 blocks
}

// round 4
// speedup vs baseline: 1.9446x; 1.6883x over previous
#include <cuda_runtime.h>
#include <cuda_bf16.h>
#include <math_constants.h>
#include <cstdint>

// Fixed shapes: b=2,h=16,s=4096,d=64,m=256
constexpr int D        = 64;
constexpr int M        = 256;
constexpr int TOKENS   = 2 * 16 * 4096;   // 131072 per tensor
constexpr int TPB_TOK  = 64;              // tokens per CTA
constexpr float NORMALIZER = 0.35355339059327379f; // 64^-0.25
constexpr float HALF_N2    = 0.0625f;     // 0.5 * normalizer^2
constexpr float RATIO      = 0.0625f;     // 256^-0.5
constexpr float EPSV       = 1e-4f;

// smem layout (offsets from 1024-aligned base)
constexpr int SM_A_HI = 0;        // 64 x 128B  (bf16 hi of data tile)
constexpr int SM_A_LO = 8192;     // 64 x 128B  (bf16 residual)
constexpr int SM_B_HI = 16384;    // 256 x 128B (bf16 hi of proj*normalizer)
constexpr int SM_B_LO = 49152;    // 256 x 128B
constexpr int SM_DIAG = 81920;    // 64 f32
constexpr int SM_SMAX = 82176;    // 4 x 64 f32
constexpr int SM_SWARP= 83200;    // 8 f32
constexpr int SMEM_BYTES = 83232 + 1024;  // + alignment slack

__device__ float g_stab[32];

__global__ void init_stab() {
    if (threadIdx.x < 32) g_stab[threadIdx.x] = -CUDART_INF_F;
}

__device__ __forceinline__ void atomicMaxFloat(float* addr, float val) {
    int* ai = (int*)addr;
    int old = *ai;
    while (__int_as_float(old) < val) {
        int assumed = old;
        old = atomicCAS(ai, assumed, __float_as_int(val));
        if (old == assumed) break;
    }
}

__device__ __forceinline__ uint32_t smem_u32(const void* p) {
    uint32_t a;
    asm("{ .reg .u64 t; cvta.to.shared.u64 t, %1; cvt.u32.u64 %0, t; }"
        : "=r"(a) : "l"(p));
    return a;
}
__device__ __forceinline__ uint32_t sw128(uint32_t off) {
    return off ^ ((off >> 3) & 0x70);
}
__device__ __forceinline__ void ldm_x4(uint32_t* r, uint32_t addr) {
    asm volatile("ldmatrix.sync.aligned.m8n8.x4.shared.b16 {%0,%1,%2,%3}, [%4];"
                 : "=r"(r[0]), "=r"(r[1]), "=r"(r[2]), "=r"(r[3]) : "r"(addr));
}
__device__ __forceinline__ void mma16816(float* c, const uint32_t* a,
                                         uint32_t b0, uint32_t b1) {
    asm volatile(
        "mma.sync.aligned.m16n8k16.row.col.f32.bf16.bf16.f32 "
        "{%0,%1,%2,%3}, {%4,%5,%6,%7}, {%8,%9}, {%0,%1,%2,%3};"
        : "+f"(c[0]), "+f"(c[1]), "+f"(c[2]), "+f"(c[3])
        : "r"(a[0]), "r"(a[1]), "r"(a[2]), "r"(a[3]), "r"(b0), "r"(b1));
}
__device__ __forceinline__ uint32_t pack_bf16x2(float a, float b) {
    __nv_bfloat162 t = __floats2bfloat162_rn(a, b);
    return *reinterpret_cast<uint32_t*>(&t);
}
// Split float4 into bf16 hi (rn) and bf16 residual lo, packed as uint2 (8B).
__device__ __forceinline__ void split_f4(float4 v, uint2& hi, uint2& lo) {
    float hx = __bfloat162float(__float2bfloat16(v.x));
    float hy = __bfloat162float(__float2bfloat16(v.y));
    float hz = __bfloat162float(__float2bfloat16(v.z));
    float hw = __bfloat162float(__float2bfloat16(v.w));
    hi.x = pack_bf16x2(hx, hy);
    hi.y = pack_bf16x2(hz, hw);
    lo.x = pack_bf16x2(v.x - hx, v.y - hy);
    lo.y = pack_bf16x2(v.z - hz, v.w - hw);
}

enum { MODE_Q = 0, MODE_K = 1, MODE_KMAX = 2 };

// CTA = 256 threads (8 warps), tile = 64 tokens x 256 features.
// Warp wid: rg = wid&1 -> rows 32*rg..+31; ch = wid>>1 -> cols 64*ch..+63.
// dash = (normalizer*x) . proj^T  via 3 bf16 products (xh*ph + xh*pl + xl*ph).
template<int MODE>
__global__ __launch_bounds__(256, 2) void proj_mma(
    const float* __restrict__ data,
    const float* __restrict__ proj,
    float* __restrict__ out)
{
    extern __shared__ char smraw[];
    char* sm = (char*)(((uintptr_t)smraw + 1023) & ~(uintptr_t)1023);
    const uint32_t s0 = smem_u32(sm);
    const int tid = threadIdx.x, lane = tid & 31, wid = tid >> 5;
    const int rg = wid & 1, ch = wid >> 1;

    // ---- stage B = proj * normalizer (256x64 f32 -> bf16 hi/lo, sw128 rows)
    {
        const float4* p4 = reinterpret_cast<const float4*>(proj);
        #pragma unroll
        for (int i = 0; i < 16; ++i) {
            int flat = tid + 256 * i;            // row = flat>>4, c4 = flat&15
            float4 v = p4[flat];
            v.x *= NORMALIZER; v.y *= NORMALIZER; v.z *= NORMALIZER; v.w *= NORMALIZER;
            uint2 hi, lo; split_f4(v, hi, lo);
            uint32_t sw = sw128((uint32_t)(flat >> 4) * 128u + (uint32_t)(flat & 15) * 8u);
            *reinterpret_cast<uint2*>(sm + SM_B_HI + sw) = hi;
            *reinterpret_cast<uint2*>(sm + SM_B_LO + sw) = lo;
        }
    }
    // ---- stage A = data tile (64x64) + diag
    {
        const float4* x4 = reinterpret_cast<const float4*>(data)
                         + (size_t)blockIdx.x * TPB_TOK * (D / 4);
        float* sdiag = reinterpret_cast<float*>(sm + SM_DIAG);
        #pragma unroll
        for (int i = 0; i < 4; ++i) {
            int flat = tid + 256 * i;            // token = flat>>4
            float4 v = x4[flat];
            if (MODE != MODE_KMAX) {
                float sq = v.x*v.x + v.y*v.y + v.z*v.z + v.w*v.w;
                sq += __shfl_down_sync(0xffffffffu, sq, 8, 16);
                sq += __shfl_down_sync(0xffffffffu, sq, 4, 16);
                sq += __shfl_down_sync(0xffffffffu, sq, 2, 16);
                sq += __shfl_down_sync(0xffffffffu, sq, 1, 16);
                if ((tid & 15) == 0) sdiag[flat >> 4] = HALF_N2 * sq;
            }
            uint2 hi, lo; split_f4(v, hi, lo);
            uint32_t sw = sw128((uint32_t)(flat >> 4) * 128u + (uint32_t)(flat & 15) * 8u);
            *reinterpret_cast<uint2*>(sm + SM_A_HI + sw) = hi;
            *reinterpret_cast<uint2*>(sm + SM_A_LO + sw) = lo;
        }
    }
    __syncthreads();

    // ---- per-thread ldmatrix offsets (canonical m8n8.x4 address pattern)
    const int arowoff = lane & 15;
    const int akoff   = (lane & 16);              // 0 or 16 bytes
    const int browoff = ((lane & 16) >> 1) + (lane & 7);
    const int bkoff   = (lane & 8) * 2;           // 0 or 16 bytes

    uint32_t asw[2][4], bsw[4];
    #pragma unroll
    for (int ks = 0; ks < 4; ++ks) {
        #pragma unroll
        for (int mt = 0; mt < 2; ++mt)
            asw[mt][ks] = sw128((uint32_t)(32*rg + 16*mt + arowoff) * 128u
                                + (uint32_t)(ks*32 + akoff));
        bsw[ks] = sw128((uint32_t)browoff * 128u + (uint32_t)(ks*32 + bkoff));
    }
    const uint32_t bbase = s0 + SM_B_HI + (uint32_t)ch * 8192u;

    float acc[2][8][4];
    #pragma unroll
    for (int mt = 0; mt < 2; ++mt)
        #pragma unroll
        for (int nt = 0; nt < 8; ++nt)
            #pragma unroll
            for (int j = 0; j < 4; ++j) acc[mt][nt][j] = 0.0f;

    #pragma unroll
    for (int ks = 0; ks < 4; ++ks) {
        uint32_t ah[2][4], al[2][4];
        ldm_x4(ah[0], s0 + SM_A_HI + asw[0][ks]);
        ldm_x4(ah[1], s0 + SM_A_HI + asw[1][ks]);
        ldm_x4(al[0], s0 + SM_A_LO + asw[0][ks]);
        ldm_x4(al[1], s0 + SM_A_LO + asw[1][ks]);
        #pragma unroll
        for (int np = 0; np < 4; ++np) {
            uint32_t bh[4], bl[4];
            ldm_x4(bh, bbase + (uint32_t)np * 2048u + bsw[ks]);
            ldm_x4(bl, bbase + 32768u + (uint32_t)np * 2048u + bsw[ks]);
            #pragma unroll
            for (int mt = 0; mt < 2; ++mt) {
                mma16816(acc[mt][2*np],   ah[mt], bh[0], bh[1]);
                mma16816(acc[mt][2*np+1], ah[mt], bh[2], bh[3]);
                mma16816(acc[mt][2*np],   ah[mt], bl[0], bl[1]);
                mma16816(acc[mt][2*np+1], ah[mt], bl[2], bl[3]);
                mma16816(acc[mt][2*np],   al[mt], bh[0], bh[1]);
                mma16816(acc[mt][2*np+1], al[mt], bh[2], bh[3]);
            }
        }
    }

    // ---- epilogues. Fragment rows: g=lane>>2 (+8); cols: nt*8 + 2*(lane&3).
    const int g = lane >> 2, t = lane & 3;

    if (MODE == MODE_KMAX) {
        float m = -CUDART_INF_F;
        #pragma unroll
        for (int mt = 0; mt < 2; ++mt)
            #pragma unroll
            for (int nt = 0; nt < 8; ++nt)
                #pragma unroll
                for (int j = 0; j < 4; ++j) m = fmaxf(m, acc[mt][nt][j]);
        #pragma unroll
        for (int off = 16; off; off >>= 1)
            m = fmaxf(m, __shfl_xor_sync(0xffffffffu, m, off));
        float* swarp = reinterpret_cast<float*>(sm + SM_SWARP);
        if (lane == 0) swarp[wid] = m;
        __syncthreads();
        if (tid == 0) {
            float mm = swarp[0];
            #pragma unroll
            for (int w = 1; w < 8; ++w) mm = fmaxf(mm, swarp[w]);
            atomicMaxFloat(&g_stab[blockIdx.x >> 6], mm);  // 64 blocks per (b,h)
        }
        return;
    }

    const float* sdiag = reinterpret_cast<const float*>(sm + SM_DIAG);
    float base[2][2];
    if (MODE == MODE_Q) {
        float* smax = reinterpret_cast<float*>(sm + SM_SMAX);  // [4 ch][64 rows]
        #pragma unroll
        for (int mt = 0; mt < 2; ++mt) {
            float m0 = -CUDART_INF_F, m1 = -CUDART_INF_F;
            #pragma unroll
            for (int nt = 0; nt < 8; ++nt) {
                m0 = fmaxf(m0, fmaxf(acc[mt][nt][0], acc[mt][nt][1]));
                m1 = fmaxf(m1, fmaxf(acc[mt][nt][2], acc[mt][nt][3]));
            }
            m0 = fmaxf(m0, __shfl_xor_sync(0xffffffffu, m0, 1));
            m0 = fmaxf(m0, __shfl_xor_sync(0xffffffffu, m0, 2));
            m1 = fmaxf(m1, __shfl_xor_sync(0xffffffffu, m1, 1));
            m1 = fmaxf(m1, __shfl_xor_sync(0xffffffffu, m1, 2));
            if (t == 0) {
                smax[ch * 64 + 32*rg + 16*mt + g]     = m0;
                smax[ch * 64 + 32*rg + 16*mt + g + 8] = m1;
            }
        }
        __syncthreads();
        #pragma unroll
        for (int mt = 0; mt < 2; ++mt)
            #pragma unroll
            for (int h = 0; h < 2; ++h) {
                int r = 32*rg + 16*mt + g + 8*h;
                float mm = fmaxf(fmaxf(smax[r], smax[64 + r]),
                                 fmaxf(smax[128 + r], smax[192 + r]));
                base[mt][h] = sdiag[r] + mm;
            }
    } else {
        const float stab = g_stab[blockIdx.x >> 6];
        #pragma unroll
        for (int mt = 0; mt < 2; ++mt)
            #pragma unroll
            for (int h = 0; h < 2; ++h)
                base[mt][h] = sdiag[32*rg + 16*mt + g + 8*h] + stab;
    }

    const long long tok0 = (long long)blockIdx.x * TPB_TOK;
    #pragma unroll
    for (int mt = 0; mt < 2; ++mt) {
        const int r0 = 32*rg + 16*mt + g;
        float* o0 = out + (tok0 + r0) * M + 64*ch + 2*t;
        float* o1 = out + (tok0 + r0 + 8) * M + 64*ch + 2*t;
        #pragma unroll
        for (int nt = 0; nt < 8; ++nt) {
            float2 e0, e1;
            e0.x = RATIO * (__expf(acc[mt][nt][0] - base[mt][0]) + EPSV);
            e0.y = RATIO * (__expf(acc[mt][nt][1] - base[mt][0]) + EPSV);
            e1.x = RATIO * (__expf(acc[mt][nt][2] - base[mt][1]) + EPSV);
            e1.y = RATIO * (__expf(acc[mt][nt][3] - base[mt][1]) + EPSV);
            *reinterpret_cast<float2*>(o0 + nt * 8) = e0;
            *reinterpret_cast<float2*>(o1 + nt * 8) = e1;
        }
    }
}

extern "C" void kernel_launch(void* const* d_in, const int* in_sizes, int n_in,
                              void* d_out, int out_size) {
    const float* q    = (const float*)d_in[0];
    const float* k    = (const float*)d_in[1];
    const float* proj = (const float*)d_in[2];

    float* out_q = (float*)d_out;
    float* out_k = out_q + (long long)TOKENS * M;

    cudaFuncSetAttribute(proj_mma<MODE_Q>,    cudaFuncAttributeMaxDynamicSharedMemorySize, SMEM_BYTES);
    cudaFuncSetAttribute(proj_mma<MODE_K>,    cudaFuncAttributeMaxDynamicSharedMemorySize, SMEM_BYTES);
    cudaFuncSetAttribute(proj_mma<MODE_KMAX>, cudaFuncAttributeMaxDynamicSharedMemorySize, SMEM_BYTES);

    constexpr int GRID = TOKENS / TPB_TOK;  // 2048
    init_stab<<<1, 32>>>();
    proj_mma<MODE_KMAX><<<GRID, 256, SMEM_BYTES>>>(k, proj, out_k);
    proj_mma<MODE_Q   ><<<GRID, 256, SMEM_BYTES>>>(q, proj, out_q);
    proj_mma<MODE_K   ><<<GRID, 256, SMEM_BYTES>>>(k, proj, out_k);
}

// round 5
// speedup vs baseline: 2.9670x; 1.5258x over previous
#include <cuda_runtime.h>
#include <cuda_bf16.h>
#include <math_constants.h>
#include <cstdint>

// Fixed shapes: b=2,h=16,s=4096,d=64,m=256
constexpr int D        = 64;
constexpr int M        = 256;
constexpr int TOKENS   = 2 * 16 * 4096;   // 131072 per tensor
constexpr int TPB_TOK  = 64;              // tokens per tile
constexpr int NTILES   = TOKENS / TPB_TOK; // 2048
constexpr int GRID_P   = 304;             // ~2 CTAs/SM persistent
constexpr float NORMALIZER = 0.35355339059327379f; // 64^-0.25
constexpr float HALF_N2    = 0.0625f;     // 0.5 * normalizer^2
constexpr float RATIO      = 0.0625f;     // 256^-0.5
constexpr float EPSV       = 1e-4f;
constexpr float OFFSET     = RATIO * EPSV;
constexpr float L2E        = 1.4426950408889634f;
constexpr float LOG2RATIO  = -4.0f;       // log2(1/16)

// smem layout (offsets from 1024-aligned base)
constexpr int SM_B_HI = 0;        // 256 x 128B  (bf16 hi of proj*normalizer, sw128)
constexpr int SM_B_LO = 32768;    // 256 x 128B
constexpr int SM_A_HI = 65536;    // 64 x 128B
constexpr int SM_A_LO = 73728;    // 64 x 128B
constexpr int SM_DIAG = 81920;    // 64 f32
constexpr int SM_SMAX = 82176;    // 4 x 64 f32
constexpr int SM_SWARP= 83200;    // 8 f32
constexpr int SMEM_BYTES = 83232 + 1024;

__device__ float g_stab[32];
__device__ float g_scale[32];
__device__ uint4 g_Bimg[4096];    // 64KB pre-swizzled bf16 hi/lo image of B

__device__ __forceinline__ void atomicMaxFloat(float* addr, float val) {
    int* ai = (int*)addr;
    int old = *ai;
    while (__int_as_float(old) < val) {
        int assumed = old;
        old = atomicCAS(ai, assumed, __float_as_int(val));
        if (old == assumed) break;
    }
}
__device__ __forceinline__ uint32_t smem_u32(const void* p) {
    uint32_t a;
    asm("{ .reg .u64 t; cvta.to.shared.u64 t, %1; cvt.u32.u64 %0, t; }"
        : "=r"(a) : "l"(p));
    return a;
}
__device__ __forceinline__ uint32_t sw128(uint32_t off) {
    return off ^ ((off >> 3) & 0x70);
}
__device__ __forceinline__ void ldm_x4(uint32_t* r, uint32_t addr) {
    asm volatile("ldmatrix.sync.aligned.m8n8.x4.shared.b16 {%0,%1,%2,%3}, [%4];"
                 : "=r"(r[0]), "=r"(r[1]), "=r"(r[2]), "=r"(r[3]) : "r"(addr));
}
__device__ __forceinline__ void mma16816(float* c, const uint32_t* a,
                                         uint32_t b0, uint32_t b1) {
    asm volatile(
        "mma.sync.aligned.m16n8k16.row.col.f32.bf16.bf16.f32 "
        "{%0,%1,%2,%3}, {%4,%5,%6,%7}, {%8,%9}, {%0,%1,%2,%3};"
        : "+f"(c[0]), "+f"(c[1]), "+f"(c[2]), "+f"(c[3])
        : "r"(a[0]), "r"(a[1]), "r"(a[2]), "r"(a[3]), "r"(b0), "r"(b1));
}
__device__ __forceinline__ float ex2(float x) {
    float r;
    asm("ex2.approx.f32 %0, %1;" : "=f"(r) : "f"(x));
    return r;
}
__device__ __forceinline__ uint32_t pack_bf16x2(float a, float b) {
    __nv_bfloat162 t = __floats2bfloat162_rn(a, b);
    return *reinterpret_cast<uint32_t*>(&t);
}
__device__ __forceinline__ void split_f4(float4 v, uint2& hi, uint2& lo) {
    float hx = __bfloat162float(__float2bfloat16(v.x));
    float hy = __bfloat162float(__float2bfloat16(v.y));
    float hz = __bfloat162float(__float2bfloat16(v.z));
    float hw = __bfloat162float(__float2bfloat16(v.w));
    hi.x = pack_bf16x2(hx, hy);
    hi.y = pack_bf16x2(hz, hw);
    lo.x = pack_bf16x2(v.x - hx, v.y - hy);
    lo.y = pack_bf16x2(v.z - hz, v.w - hw);
}

// One-shot: init stab + build pre-swizzled bf16 hi/lo image of proj*normalizer.
__global__ void prep_B(const float* __restrict__ proj) {
    int tid = threadIdx.x;
    if (tid < 32) g_stab[tid] = -CUDART_INF_F;
    char* dst = reinterpret_cast<char*>(g_Bimg);
    const float4* p4 = reinterpret_cast<const float4*>(proj);
    #pragma unroll
    for (int i = 0; i < 16; ++i) {
        int flat = tid + 256 * i;            // row = flat>>4, c4 = flat&15
        float4 v = p4[flat];
        v.x *= NORMALIZER; v.y *= NORMALIZER; v.z *= NORMALIZER; v.w *= NORMALIZER;
        uint2 hi, lo; split_f4(v, hi, lo);
        uint32_t sw = sw128((uint32_t)(flat >> 4) * 128u + (uint32_t)(flat & 15) * 8u);
        *reinterpret_cast<uint2*>(dst + sw)          = hi;
        *reinterpret_cast<uint2*>(dst + 32768u + sw) = lo;
    }
}

__global__ void prep_scale() {
    if (threadIdx.x < 32) g_scale[threadIdx.x] = RATIO * __expf(-g_stab[threadIdx.x]);
}

enum { MODE_Q = 0, MODE_K = 1 };

// Persistent CTA: copies B image once, loops over 64-token tiles.
// Warp wid: rg = wid&1 -> rows 32*rg..+31; ch = wid>>1 -> cols 64*ch..+63.
template<int MODE>
__global__ __launch_bounds__(256, 2) void proj_mma(
    const float* __restrict__ data,
    float* __restrict__ out)
{
    extern __shared__ char smraw[];
    char* sm = (char*)(((uintptr_t)smraw + 1023) & ~(uintptr_t)1023);
    const uint32_t s0 = smem_u32(sm);
    const int tid = threadIdx.x, lane = tid & 31, wid = tid >> 5;
    const int rg = wid & 1, ch = wid >> 1;

    // ---- copy pre-swizzled B image (64KB) into smem once
    {
        uint4* smB = reinterpret_cast<uint4*>(sm + SM_B_HI);
        #pragma unroll
        for (int i = 0; i < 16; ++i) smB[tid + 256 * i] = g_Bimg[tid + 256 * i];
    }

    // ---- hoisted ldmatrix offsets
    const int arowoff = lane & 15;
    const int akoff   = (lane & 16);
    const int browoff = ((lane & 16) >> 1) + (lane & 7);
    const int bkoff   = (lane & 8) * 2;
    uint32_t aaddr[2][4], bhaddr[4], bladdr[4];
    #pragma unroll
    for (int ks = 0; ks < 4; ++ks) {
        #pragma unroll
        for (int mt = 0; mt < 2; ++mt)
            aaddr[mt][ks] = s0 + SM_A_HI + sw128(
                (uint32_t)(32*rg + 16*mt + arowoff) * 128u + (uint32_t)(ks*32 + akoff));
        uint32_t bsw = sw128((uint32_t)browoff * 128u + (uint32_t)(ks*32 + bkoff));
        bhaddr[ks] = s0 + SM_B_HI + (uint32_t)ch * 8192u + bsw;
        bladdr[ks] = s0 + SM_B_LO + (uint32_t)ch * 8192u + bsw;
    }
    const int g = lane >> 2, t = lane & 3;
    float* sdiag = reinterpret_cast<float*>(sm + SM_DIAG);
    float* smax  = reinterpret_cast<float*>(sm + SM_SMAX);
    float* swarp = reinterpret_cast<float*>(sm + SM_SWARP);

    for (int tile = blockIdx.x; tile < NTILES; tile += GRID_P) {
        __syncthreads();   // previous iter's sdiag/smax consumers done; B copy done (iter 0)

        // ---- stage A tile (64x64) + diag
        {
            const float4* x4 = reinterpret_cast<const float4*>(data)
                             + (size_t)tile * TPB_TOK * (D / 4);
            #pragma unroll
            for (int i = 0; i < 4; ++i) {
                int flat = tid + 256 * i;        // token = flat>>4
                float4 v = x4[flat];
                float sq = v.x*v.x + v.y*v.y + v.z*v.z + v.w*v.w;
                sq += __shfl_down_sync(0xffffffffu, sq, 8, 16);
                sq += __shfl_down_sync(0xffffffffu, sq, 4, 16);
                sq += __shfl_down_sync(0xffffffffu, sq, 2, 16);
                sq += __shfl_down_sync(0xffffffffu, sq, 1, 16);
                if ((tid & 15) == 0) sdiag[flat >> 4] = HALF_N2 * sq;
                uint2 hi, lo; split_f4(v, hi, lo);
                uint32_t sw = sw128((uint32_t)(flat >> 4) * 128u + (uint32_t)(flat & 15) * 8u);
                *reinterpret_cast<uint2*>(sm + SM_A_HI + sw) = hi;
                *reinterpret_cast<uint2*>(sm + SM_A_LO + sw) = lo;
            }
        }
        __syncthreads();

        // ---- 3-product bf16 GEMM: xh*ph + xh*pl + xl*ph
        float acc[2][8][4];
        #pragma unroll
        for (int mt = 0; mt < 2; ++mt)
            #pragma unroll
            for (int nt = 0; nt < 8; ++nt)
                #pragma unroll
                for (int j = 0; j < 4; ++j) acc[mt][nt][j] = 0.0f;

        #pragma unroll
        for (int ks = 0; ks < 4; ++ks) {
            uint32_t ah[2][4], al[2][4];
            ldm_x4(ah[0], aaddr[0][ks]);
            ldm_x4(ah[1], aaddr[1][ks]);
            ldm_x4(al[0], aaddr[0][ks] + 8192u);   // A_LO mirrors A_HI at +8KB
            ldm_x4(al[1], aaddr[1][ks] + 8192u);
            #pragma unroll
            for (int np = 0; np < 4; ++np) {
                uint32_t bh[4], bl[4];
                ldm_x4(bh, bhaddr[ks] + (uint32_t)np * 2048u);
                ldm_x4(bl, bladdr[ks] + (uint32_t)np * 2048u);
                #pragma unroll
                for (int mt = 0; mt < 2; ++mt) {
                    mma16816(acc[mt][2*np],   ah[mt], bh[0], bh[1]);
                    mma16816(acc[mt][2*np+1], ah[mt], bh[2], bh[3]);
                    mma16816(acc[mt][2*np],   ah[mt], bl[0], bl[1]);
                    mma16816(acc[mt][2*np+1], ah[mt], bl[2], bl[3]);
                    mma16816(acc[mt][2*np],   al[mt], bh[0], bh[1]);
                    mma16816(acc[mt][2*np+1], al[mt], bh[2], bh[3]);
                }
            }
        }

        // ---- epilogue. Fragment rows: g (+8); cols: nt*8 + 2*t.
        const long long tok0 = (long long)tile * TPB_TOK;
        float cb[2][2];

        if (MODE == MODE_Q) {
            #pragma unroll
            for (int mt = 0; mt < 2; ++mt) {
                float m0 = -CUDART_INF_F, m1 = -CUDART_INF_F;
                #pragma unroll
                for (int nt = 0; nt < 8; ++nt) {
                    m0 = fmaxf(m0, fmaxf(acc[mt][nt][0], acc[mt][nt][1]));
                    m1 = fmaxf(m1, fmaxf(acc[mt][nt][2], acc[mt][nt][3]));
                }
                m0 = fmaxf(m0, __shfl_xor_sync(0xffffffffu, m0, 1));
                m0 = fmaxf(m0, __shfl_xor_sync(0xffffffffu, m0, 2));
                m1 = fmaxf(m1, __shfl_xor_sync(0xffffffffu, m1, 1));
                m1 = fmaxf(m1, __shfl_xor_sync(0xffffffffu, m1, 2));
                if (t == 0) {
                    smax[ch * 64 + 32*rg + 16*mt + g]     = m0;
                    smax[ch * 64 + 32*rg + 16*mt + g + 8] = m1;
                }
            }
            __syncthreads();
            #pragma unroll
            for (int mt = 0; mt < 2; ++mt)
                #pragma unroll
                for (int h = 0; h < 2; ++h) {
                    int r = 32*rg + 16*mt + g + 8*h;
                    float mm = fmaxf(fmaxf(smax[r], smax[64 + r]),
                                     fmaxf(smax[128 + r], smax[192 + r]));
                    cb[mt][h] = LOG2RATIO - (sdiag[r] + mm) * L2E;
                }
            #pragma unroll
            for (int mt = 0; mt < 2; ++mt) {
                const int r0 = 32*rg + 16*mt + g;
                float* o0 = out + (tok0 + r0) * M + 64*ch + 2*t;
                float* o1 = out + (tok0 + r0 + 8) * M + 64*ch + 2*t;
                #pragma unroll
                for (int nt = 0; nt < 8; ++nt) {
                    float2 e0, e1;
                    e0.x = ex2(fmaf(acc[mt][nt][0], L2E, cb[mt][0])) + OFFSET;
                    e0.y = ex2(fmaf(acc[mt][nt][1], L2E, cb[mt][0])) + OFFSET;
                    e1.x = ex2(fmaf(acc[mt][nt][2], L2E, cb[mt][1])) + OFFSET;
                    e1.y = ex2(fmaf(acc[mt][nt][3], L2E, cb[mt][1])) + OFFSET;
                    *reinterpret_cast<float2*>(o0 + nt * 8) = e0;
                    *reinterpret_cast<float2*>(o1 + nt * 8) = e1;
                }
            }
        } else {
            // K: store E = exp(dash - diag) (via ex2), track max(dash) for stab
            float mx = -CUDART_INF_F;
            #pragma unroll
            for (int mt = 0; mt < 2; ++mt)
                #pragma unroll
                for (int h = 0; h < 2; ++h)
                    cb[mt][h] = -sdiag[32*rg + 16*mt + g + 8*h] * L2E;
            #pragma unroll
            for (int mt = 0; mt < 2; ++mt) {
                const int r0 = 32*rg + 16*mt + g;
                float* o0 = out + (tok0 + r0) * M + 64*ch + 2*t;
                float* o1 = out + (tok0 + r0 + 8) * M + 64*ch + 2*t;
                #pragma unroll
                for (int nt = 0; nt < 8; ++nt) {
                    float2 e0, e1;
                    mx = fmaxf(mx, fmaxf(fmaxf(acc[mt][nt][0], acc[mt][nt][1]),
                                         fmaxf(acc[mt][nt][2], acc[mt][nt][3])));
                    e0.x = ex2(fmaf(acc[mt][nt][0], L2E, cb[mt][0]));
                    e0.y = ex2(fmaf(acc[mt][nt][1], L2E, cb[mt][0]));
                    e1.x = ex2(fmaf(acc[mt][nt][2], L2E, cb[mt][1]));
                    e1.y = ex2(fmaf(acc[mt][nt][3], L2E, cb[mt][1]));
                    *reinterpret_cast<float2*>(o0 + nt * 8) = e0;
                    *reinterpret_cast<float2*>(o1 + nt * 8) = e1;
                }
            }
            #pragma unroll
            for (int off = 16; off; off >>= 1)
                mx = fmaxf(mx, __shfl_xor_sync(0xffffffffu, mx, off));
            if (lane == 0) swarp[wid] = mx;
            __syncthreads();
            if (tid == 0) {
                float mm = swarp[0];
                #pragma unroll
                for (int w = 1; w < 8; ++w) mm = fmaxf(mm, swarp[w]);
                atomicMaxFloat(&g_stab[tile >> 6], mm);  // 64 tiles per (b,h)
            }
        }
    }
}

// k pass 2: out = scale[bh] * E + ratio*eps  (DRAM-bound streaming)
__global__ void finalize_k(float* __restrict__ kout) {
    constexpr long long HALF4 = (long long)TOKENS * M / 4 / 2;
    long long i = (long long)blockIdx.x * blockDim.x + threadIdx.x;
    float4* p4 = reinterpret_cast<float4*>(kout);
    #pragma unroll
    for (int h = 0; h < 2; ++h) {
        long long idx = i + h * HALF4;
        float4 v = p4[idx];
        float scale = g_scale[(int)(idx >> 18)];  // 2^18 float4 per (b,h)
        v.x = fmaf(scale, v.x, OFFSET);
        v.y = fmaf(scale, v.y, OFFSET);
        v.z = fmaf(scale, v.z, OFFSET);
        v.w = fmaf(scale, v.w, OFFSET);
        p4[idx] = v;
    }
}

extern "C" void kernel_launch(void* const* d_in, const int* in_sizes, int n_in,
                              void* d_out, int out_size) {
    const float* q    = (const float*)d_in[0];
    const float* k    = (const float*)d_in[1];
    const float* proj = (const float*)d_in[2];

    float* out_q = (float*)d_out;
    float* out_k = out_q + (long long)TOKENS * M;

    cudaFuncSetAttribute(proj_mma<MODE_Q>, cudaFuncAttributeMaxDynamicSharedMemorySize, SMEM_BYTES);
    cudaFuncSetAttribute(proj_mma<MODE_K>, cudaFuncAttributeMaxDynamicSharedMemorySize, SMEM_BYTES);

    prep_B<<<1, 256>>>(proj);
    proj_mma<MODE_Q><<<GRID_P, 256, SMEM_BYTES>>>(q, out_q);
    proj_mma<MODE_K><<<GRID_P, 256, SMEM_BYTES>>>(k, out_k);
    prep_scale<<<1, 32>>>();

    constexpr long long HALF4 = (long long)TOKENS * M / 4 / 2;
    finalize_k<<<(int)(HALF4 / 256), 256>>>(out_k);
}

// round 6
// speedup vs baseline: 3.3501x; 1.1291x over previous
#include <cuda_runtime.h>
#include <cuda_bf16.h>
#include <math_constants.h>
#include <cstdint>

// Fixed shapes: b=2,h=16,s=4096,d=64,m=256
constexpr int D        = 64;
constexpr int M        = 256;
constexpr int TOKENS   = 2 * 16 * 4096;    // 131072 per tensor
constexpr int TPB_TOK  = 64;               // tokens per tile
constexpr int NTILES   = TOKENS / TPB_TOK; // 2048 per tensor
constexpr int GRID_P   = 304;              // 2 CTAs/SM persistent (152 SMs)
constexpr float NORMALIZER = 0.35355339059327379f; // 64^-0.25
constexpr float HALF_N2    = 0.0625f;      // 0.5 * normalizer^2
constexpr float RATIO      = 0.0625f;      // 256^-0.5
constexpr float EPSV       = 1e-4f;
constexpr float OFFSET     = RATIO * EPSV;
constexpr float L2E        = 1.4426950408889634f;
constexpr float LOG2RATIO  = -4.0f;        // log2(1/16)

// smem layout (offsets from 1024-aligned base)
constexpr int SM_B_HI = 0;        // 256 x 128B (bf16 hi of proj*normalizer, sw128)
constexpr int SM_B_LO = 32768;    // 256 x 128B
constexpr int SM_A_HI = 65536;    // 64 x 128B
constexpr int SM_A_LO = 73728;    // 64 x 128B
constexpr int SM_RAW  = 81920;    // 16KB raw fp32 A staging (cp.async target)
constexpr int SM_DIAG = 98304;    // 64 f32
constexpr int SM_SMAX = 98560;    // 4 x 64 f32
constexpr int SM_SWARP= 99584;    // 8 f32
constexpr int SMEM_BYTES = 99616 + 1024;

__device__ float g_stab[32];
__device__ uint4 g_Bimg[4096];    // 64KB pre-swizzled bf16 hi/lo image of B

__device__ __forceinline__ void atomicMaxFloat(float* addr, float val) {
    int* ai = (int*)addr;
    int old = *ai;
    while (__int_as_float(old) < val) {
        int assumed = old;
        old = atomicCAS(ai, assumed, __float_as_int(val));
        if (old == assumed) break;
    }
}
__device__ __forceinline__ uint32_t smem_u32(const void* p) {
    uint32_t a;
    asm("{ .reg .u64 t; cvta.to.shared.u64 t, %1; cvt.u32.u64 %0, t; }"
        : "=r"(a) : "l"(p));
    return a;
}
__device__ __forceinline__ uint32_t sw128(uint32_t off) {
    return off ^ ((off >> 3) & 0x70);
}
__device__ __forceinline__ void ldm_x4(uint32_t* r, uint32_t addr) {
    asm volatile("ldmatrix.sync.aligned.m8n8.x4.shared.b16 {%0,%1,%2,%3}, [%4];"
                 : "=r"(r[0]), "=r"(r[1]), "=r"(r[2]), "=r"(r[3]) : "r"(addr));
}
__device__ __forceinline__ void mma16816(float* c, const uint32_t* a,
                                         uint32_t b0, uint32_t b1) {
    asm volatile(
        "mma.sync.aligned.m16n8k16.row.col.f32.bf16.bf16.f32 "
        "{%0,%1,%2,%3}, {%4,%5,%6,%7}, {%8,%9}, {%0,%1,%2,%3};"
        : "+f"(c[0]), "+f"(c[1]), "+f"(c[2]), "+f"(c[3])
        : "r"(a[0]), "r"(a[1]), "r"(a[2]), "r"(a[3]), "r"(b0), "r"(b1));
}
__device__ __forceinline__ float ex2(float x) {
    float r;
    asm("ex2.approx.f32 %0, %1;" : "=f"(r) : "f"(x));
    return r;
}
__device__ __forceinline__ void cp_async16(uint32_t smem_dst, const void* gsrc) {
    asm volatile("cp.async.cg.shared.global [%0], [%1], 16;"
                 :: "r"(smem_dst), "l"(gsrc) : "memory");
}
__device__ __forceinline__ void cp_commit() {
    asm volatile("cp.async.commit_group;" ::: "memory");
}
__device__ __forceinline__ void cp_wait0() {
    asm volatile("cp.async.wait_group 0;" ::: "memory");
}
__device__ __forceinline__ uint32_t pack_bf16x2(float a, float b) {
    __nv_bfloat162 t = __floats2bfloat162_rn(a, b);
    return *reinterpret_cast<uint32_t*>(&t);
}
__device__ __forceinline__ void split_f4(float4 v, uint2& hi, uint2& lo) {
    float hx = __bfloat162float(__float2bfloat16(v.x));
    float hy = __bfloat162float(__float2bfloat16(v.y));
    float hz = __bfloat162float(__float2bfloat16(v.z));
    float hw = __bfloat162float(__float2bfloat16(v.w));
    hi.x = pack_bf16x2(hx, hy);
    hi.y = pack_bf16x2(hz, hw);
    lo.x = pack_bf16x2(v.x - hx, v.y - hy);
    lo.y = pack_bf16x2(v.z - hz, v.w - hw);
}

// One-shot: init stab + build pre-swizzled bf16 hi/lo image of proj*normalizer.
__global__ void prep_B(const float* __restrict__ proj) {
    int tid = threadIdx.x;
    if (tid < 32) g_stab[tid] = -CUDART_INF_F;
    char* dst = reinterpret_cast<char*>(g_Bimg);
    const float4* p4 = reinterpret_cast<const float4*>(proj);
    #pragma unroll
    for (int i = 0; i < 16; ++i) {
        int flat = tid + 256 * i;            // row = flat>>4, c4 = flat&15
        float4 v = p4[flat];
        v.x *= NORMALIZER; v.y *= NORMALIZER; v.z *= NORMALIZER; v.w *= NORMALIZER;
        uint2 hi, lo; split_f4(v, hi, lo);
        uint32_t sw = sw128((uint32_t)(flat >> 4) * 128u + (uint32_t)(flat & 15) * 8u);
        *reinterpret_cast<uint2*>(dst + sw)          = hi;
        *reinterpret_cast<uint2*>(dst + 32768u + sw) = lo;
    }
}

// Fused persistent kernel: tiles [0,2048) = q, [2048,4096) = k.
// Warp wid: rg = wid&1 -> rows 32*rg..+31; ch = wid>>1 -> cols 64*ch..+63.
__global__ __launch_bounds__(256, 2) void proj_fused(
    const float* __restrict__ qdat,
    const float* __restrict__ kdat,
    float* __restrict__ out_q,
    float* __restrict__ out_k)
{
    extern __shared__ char smraw[];
    char* sm = (char*)(((uintptr_t)smraw + 1023) & ~(uintptr_t)1023);
    const uint32_t s0 = smem_u32(sm);
    const int tid = threadIdx.x, lane = tid & 31, wid = tid >> 5;
    const int rg = wid & 1, ch = wid >> 1;

    // ---- copy pre-swizzled B image (64KB) into smem once
    {
        uint4* smB = reinterpret_cast<uint4*>(sm + SM_B_HI);
        #pragma unroll
        for (int i = 0; i < 16; ++i) smB[tid + 256 * i] = g_Bimg[tid + 256 * i];
    }

    // ---- hoisted ldmatrix addresses
    const int arowoff = lane & 15;
    const int akoff   = (lane & 16);
    const int browoff = ((lane & 16) >> 1) + (lane & 7);
    const int bkoff   = (lane & 8) * 2;
    uint32_t aaddr[2][4], bhaddr[4], bladdr[4];
    #pragma unroll
    for (int ks = 0; ks < 4; ++ks) {
        #pragma unroll
        for (int mt = 0; mt < 2; ++mt)
            aaddr[mt][ks] = s0 + SM_A_HI + sw128(
                (uint32_t)(32*rg + 16*mt + arowoff) * 128u + (uint32_t)(ks*32 + akoff));
        uint32_t bsw = sw128((uint32_t)browoff * 128u + (uint32_t)(ks*32 + bkoff));
        bhaddr[ks] = s0 + SM_B_HI + (uint32_t)ch * 8192u + bsw;
        bladdr[ks] = s0 + SM_B_LO + (uint32_t)ch * 8192u + bsw;
    }
    const int g = lane >> 2, t = lane & 3;
    float* sdiag = reinterpret_cast<float*>(sm + SM_DIAG);
    float* smax  = reinterpret_cast<float*>(sm + SM_SMAX);
    float* swarp = reinterpret_cast<float*>(sm + SM_SWARP);
    float4* raw  = reinterpret_cast<float4*>(sm + SM_RAW);
    const uint32_t raw0 = s0 + SM_RAW;

    // ---- prefetch first tile's raw A via cp.async (thread tid owns flats tid+256i)
    {
        const float* src = (blockIdx.x < NTILES) ? qdat : kdat;
        int dtile = (blockIdx.x < NTILES) ? blockIdx.x : blockIdx.x - NTILES;
        const float4* x4 = reinterpret_cast<const float4*>(src)
                         + (size_t)dtile * TPB_TOK * (D / 4);
        #pragma unroll
        for (int i = 0; i < 4; ++i) {
            int flat = tid + 256 * i;
            cp_async16(raw0 + (uint32_t)flat * 16u, x4 + flat);
        }
        cp_commit();
    }

    for (int tile = blockIdx.x; tile < 2 * NTILES; tile += GRID_P) {
        const bool isQ = tile < NTILES;
        const int dtile = isQ ? tile : tile - NTILES;
        float* out = isQ ? out_q : out_k;

        cp_wait0();
        __syncthreads();   // prev iter's GEMM/epilogue done with A smem + sdiag

        // ---- convert raw -> bf16 hi/lo A tiles + diag
        #pragma unroll
        for (int i = 0; i < 4; ++i) {
            int flat = tid + 256 * i;          // token = flat>>4
            float4 v = raw[flat];
            float sq = v.x*v.x + v.y*v.y + v.z*v.z + v.w*v.w;
            sq += __shfl_down_sync(0xffffffffu, sq, 8, 16);
            sq += __shfl_down_sync(0xffffffffu, sq, 4, 16);
            sq += __shfl_down_sync(0xffffffffu, sq, 2, 16);
            sq += __shfl_down_sync(0xffffffffu, sq, 1, 16);
            if ((tid & 15) == 0) sdiag[flat >> 4] = HALF_N2 * sq;
            uint2 hi, lo; split_f4(v, hi, lo);
            uint32_t sw = sw128((uint32_t)(flat >> 4) * 128u + (uint32_t)(flat & 15) * 8u);
            *reinterpret_cast<uint2*>(sm + SM_A_HI + sw) = hi;
            *reinterpret_cast<uint2*>(sm + SM_A_LO + sw) = lo;
        }
        __syncthreads();   // A smem + sdiag visible; raw free for next prefetch

        // ---- prefetch next tile's raw A (overlaps with GEMM + epilogue)
        {
            int ntile = tile + GRID_P;
            if (ntile < 2 * NTILES) {
                const float* src = (ntile < NTILES) ? qdat : kdat;
                int ndt = (ntile < NTILES) ? ntile : ntile - NTILES;
                const float4* x4 = reinterpret_cast<const float4*>(src)
                                 + (size_t)ndt * TPB_TOK * (D / 4);
                #pragma unroll
                for (int i = 0; i < 4; ++i) {
                    int flat = tid + 256 * i;
                    cp_async16(raw0 + (uint32_t)flat * 16u, x4 + flat);
                }
            }
            cp_commit();
        }

        // ---- GEMM: 3 product phases per k-step (acc reuse distance = 16 mmas)
        float acc[2][8][4];
        #pragma unroll
        for (int mt = 0; mt < 2; ++mt)
            #pragma unroll
            for (int nt = 0; nt < 8; ++nt)
                #pragma unroll
                for (int j = 0; j < 4; ++j) acc[mt][nt][j] = 0.0f;

        #pragma unroll
        for (int ks = 0; ks < 4; ++ks) {
            uint32_t ah[2][4], al[2][4];
            ldm_x4(ah[0], aaddr[0][ks]);
            ldm_x4(ah[1], aaddr[1][ks]);
            ldm_x4(al[0], aaddr[0][ks] + 8192u);   // A_LO mirrors A_HI at +8KB
            ldm_x4(al[1], aaddr[1][ks] + 8192u);
            // phase 1: ah * bh
            #pragma unroll
            for (int np = 0; np < 4; ++np) {
                uint32_t b[4];
                ldm_x4(b, bhaddr[ks] + (uint32_t)np * 2048u);
                #pragma unroll
                for (int mt = 0; mt < 2; ++mt) {
                    mma16816(acc[mt][2*np],   ah[mt], b[0], b[1]);
                    mma16816(acc[mt][2*np+1], ah[mt], b[2], b[3]);
                }
            }
            // phase 2: ah * bl
            #pragma unroll
            for (int np = 0; np < 4; ++np) {
                uint32_t b[4];
                ldm_x4(b, bladdr[ks] + (uint32_t)np * 2048u);
                #pragma unroll
                for (int mt = 0; mt < 2; ++mt) {
                    mma16816(acc[mt][2*np],   ah[mt], b[0], b[1]);
                    mma16816(acc[mt][2*np+1], ah[mt], b[2], b[3]);
                }
            }
            // phase 3: al * bh (reload bh)
            #pragma unroll
            for (int np = 0; np < 4; ++np) {
                uint32_t b[4];
                ldm_x4(b, bhaddr[ks] + (uint32_t)np * 2048u);
                #pragma unroll
                for (int mt = 0; mt < 2; ++mt) {
                    mma16816(acc[mt][2*np],   al[mt], b[0], b[1]);
                    mma16816(acc[mt][2*np+1], al[mt], b[2], b[3]);
                }
            }
        }

        // ---- epilogue. Fragment rows: g (+8); cols: nt*8 + 2*t.
        const long long tok0 = (long long)dtile * TPB_TOK;
        float cb[2][2];

        if (isQ) {
            #pragma unroll
            for (int mt = 0; mt < 2; ++mt) {
                float m0 = -CUDART_INF_F, m1 = -CUDART_INF_F;
                #pragma unroll
                for (int nt = 0; nt < 8; ++nt) {
                    m0 = fmaxf(m0, fmaxf(acc[mt][nt][0], acc[mt][nt][1]));
                    m1 = fmaxf(m1, fmaxf(acc[mt][nt][2], acc[mt][nt][3]));
                }
                m0 = fmaxf(m0, __shfl_xor_sync(0xffffffffu, m0, 1));
                m0 = fmaxf(m0, __shfl_xor_sync(0xffffffffu, m0, 2));
                m1 = fmaxf(m1, __shfl_xor_sync(0xffffffffu, m1, 1));
                m1 = fmaxf(m1, __shfl_xor_sync(0xffffffffu, m1, 2));
                if (t == 0) {
                    smax[ch * 64 + 32*rg + 16*mt + g]     = m0;
                    smax[ch * 64 + 32*rg + 16*mt + g + 8] = m1;
                }
            }
            __syncthreads();
            #pragma unroll
            for (int mt = 0; mt < 2; ++mt)
                #pragma unroll
                for (int h = 0; h < 2; ++h) {
                    int r = 32*rg + 16*mt + g + 8*h;
                    float mm = fmaxf(fmaxf(smax[r], smax[64 + r]),
                                     fmaxf(smax[128 + r], smax[192 + r]));
                    cb[mt][h] = LOG2RATIO - (sdiag[r] + mm) * L2E;
                }
            #pragma unroll
            for (int mt = 0; mt < 2; ++mt) {
                const int r0 = 32*rg + 16*mt + g;
                float* o0 = out + (tok0 + r0) * M + 64*ch + 2*t;
                float* o1 = out + (tok0 + r0 + 8) * M + 64*ch + 2*t;
                #pragma unroll
                for (int nt = 0; nt < 8; ++nt) {
                    float2 e0, e1;
                    e0.x = ex2(fmaf(acc[mt][nt][0], L2E, cb[mt][0])) + OFFSET;
                    e0.y = ex2(fmaf(acc[mt][nt][1], L2E, cb[mt][0])) + OFFSET;
                    e1.x = ex2(fmaf(acc[mt][nt][2], L2E, cb[mt][1])) + OFFSET;
                    e1.y = ex2(fmaf(acc[mt][nt][3], L2E, cb[mt][1])) + OFFSET;
                    *reinterpret_cast<float2*>(o0 + nt * 8) = e0;
                    *reinterpret_cast<float2*>(o1 + nt * 8) = e1;
                }
            }
        } else {
            // K: store E = exp(dash - diag), track max(dash) for stab
            float mx = -CUDART_INF_F;
            #pragma unroll
            for (int mt = 0; mt < 2; ++mt)
                #pragma unroll
                for (int h = 0; h < 2; ++h)
                    cb[mt][h] = -sdiag[32*rg + 16*mt + g + 8*h] * L2E;
            #pragma unroll
            for (int mt = 0; mt < 2; ++mt) {
                const int r0 = 32*rg + 16*mt + g;
                float* o0 = out + (tok0 + r0) * M + 64*ch + 2*t;
                float* o1 = out + (tok0 + r0 + 8) * M + 64*ch + 2*t;
                #pragma unroll
                for (int nt = 0; nt < 8; ++nt) {
                    float2 e0, e1;
                    mx = fmaxf(mx, fmaxf(fmaxf(acc[mt][nt][0], acc[mt][nt][1]),
                                         fmaxf(acc[mt][nt][2], acc[mt][nt][3])));
                    e0.x = ex2(fmaf(acc[mt][nt][0], L2E, cb[mt][0]));
                    e0.y = ex2(fmaf(acc[mt][nt][1], L2E, cb[mt][0]));
                    e1.x = ex2(fmaf(acc[mt][nt][2], L2E, cb[mt][1]));
                    e1.y = ex2(fmaf(acc[mt][nt][3], L2E, cb[mt][1]));
                    *reinterpret_cast<float2*>(o0 + nt * 8) = e0;
                    *reinterpret_cast<float2*>(o1 + nt * 8) = e1;
                }
            }
            #pragma unroll
            for (int off = 16; off; off >>= 1)
                mx = fmaxf(mx, __shfl_xor_sync(0xffffffffu, mx, off));
            if (lane == 0) swarp[wid] = mx;
            __syncthreads();
            if (tid == 0) {
                float mm = swarp[0];
                #pragma unroll
                for (int w = 1; w < 8; ++w) mm = fmaxf(mm, swarp[w]);
                atomicMaxFloat(&g_stab[dtile >> 6], mm);  // 64 tiles per (b,h)
            }
        }
    }
}

// k pass 2: out = (ratio*exp(-stab[bh])) * E + ratio*eps  (DRAM-bound)
__global__ void finalize_k(float* __restrict__ kout) {
    constexpr long long HALF4 = (long long)TOKENS * M / 4 / 2;
    long long i = (long long)blockIdx.x * blockDim.x + threadIdx.x;
    float4* p4 = reinterpret_cast<float4*>(kout);
    #pragma unroll
    for (int h = 0; h < 2; ++h) {
        long long idx = i + h * HALF4;
        float4 v = p4[idx];
        float scale = RATIO * __expf(-g_stab[(int)(idx >> 18)]);  // 2^18 f4 per (b,h)
        v.x = fmaf(scale, v.x, OFFSET);
        v.y = fmaf(scale, v.y, OFFSET);
        v.z = fmaf(scale, v.z, OFFSET);
        v.w = fmaf(scale, v.w, OFFSET);
        p4[idx] = v;
    }
}

extern "C" void kernel_launch(void* const* d_in, const int* in_sizes, int n_in,
                              void* d_out, int out_size) {
    const float* q    = (const float*)d_in[0];
    const float* k    = (const float*)d_in[1];
    const float* proj = (const float*)d_in[2];

    float* out_q = (float*)d_out;
    float* out_k = out_q + (long long)TOKENS * M;

    cudaFuncSetAttribute(proj_fused, cudaFuncAttributeMaxDynamicSharedMemorySize, SMEM_BYTES);

    prep_B<<<1, 256>>>(proj);
    proj_fused<<<GRID_P, 256, SMEM_BYTES>>>(q, k, out_q, out_k);

    constexpr long long HALF4 = (long long)TOKENS * M / 4 / 2;
    finalize_k<<<(int)(HALF4 / 256), 256>>>(out_k);
}